// round 13
// baseline (speedup 1.0000x reference)
#include <cuda_runtime.h>
#include <cuda_bf16.h>
#include <cstdint>

typedef uint32_t u32;

// ---- smem layout (bytes) ----
#define PANEL_BYTES 4224                        // 132 rows x 32B (16ch bf16)
#define OFF_AHI 0                               // ring of 4 input rows (hi)
#define OFF_ALO (4 * PANEL_BYTES)               // 16896 (lo ring)
#define OFF_B   (8 * PANEL_BYTES)               // 33792: [2 var][9 pos][32 f][32B]
#define B_TILE  1024
#define OFF_STAGE (OFF_B + 18 * B_TILE)         // 52224
#define STAGE_ROW_BYTES 8704                    // 16 ch x 34 x 16B
#define OFF_OUT (OFF_STAGE + 2 * STAGE_ROW_BYTES)      // 69632
#define OUT_ROW_FLOATS 132                      // padded px stride (floats)
#define OUT_Y_FLOATS (32 * OUT_ROW_FLOATS)      // 4224 floats per y-row
#define SMEM_TOTAL (OFF_OUT + 2 * OUT_Y_FLOATS * 4)    // 69632 + 33792 = 103424

// row/half -> swizzled byte offset inside a 32B-row panel (conflict-free LDSM)
#define ADDRSWZ(r, half16) ((((u32)(r) << 5) + (half16)) ^ (((r) & 4) << 2))

#define CP_COMMIT() asm volatile("cp.async.commit_group;" ::: "memory")
#define CP_WAIT0()  asm volatile("cp.async.wait_group 0;" ::: "memory")

__device__ __forceinline__ u32 smem_u32(const void* p) {
    u32 a;
    asm("{ .reg .u64 t; cvta.to.shared.u64 t, %1; cvt.u32.u64 %0, t; }" : "=r"(a) : "l"(p));
    return a;
}

__device__ __forceinline__ void cp_async16(u32 dst, const void* src, u32 bytes) {
    asm volatile("cp.async.ca.shared.global [%0], [%1], 16, %2;"
                 :: "r"(dst), "l"(src), "r"(bytes) : "memory");
}

__device__ __forceinline__ void ldsm_x4(u32* r, u32 addr) {
    asm volatile("ldmatrix.sync.aligned.m8n8.x4.shared.b16 {%0,%1,%2,%3}, [%4];"
                 : "=r"(r[0]), "=r"(r[1]), "=r"(r[2]), "=r"(r[3]) : "r"(addr));
}

__device__ __forceinline__ void mma16816(float* d, const u32* a, const u32* b) {
    asm volatile(
        "mma.sync.aligned.m16n8k16.row.col.f32.bf16.bf16.f32 "
        "{%0,%1,%2,%3}, {%4,%5,%6,%7}, {%8,%9}, {%0,%1,%2,%3};"
        : "+f"(d[0]), "+f"(d[1]), "+f"(d[2]), "+f"(d[3])
        : "r"(a[0]), "r"(a[1]), "r"(a[2]), "r"(a[3]), "r"(b[0]), "r"(b[1]));
}

// ---- stage one raw input row (16 ch x 136 px window) via cp.async ----
__device__ __forceinline__ void stage_row(u32 sb, const float* __restrict__ x,
                                          int b, int x0, int gy, int par) {
    const bool rowOK = (gy >= 0) && (gy < 256);
    const int gyc = rowOK ? gy : 0;
    const float* xrow = x + (((u32)b * 16) << 16) + (gyc << 8);
    const int tid = threadIdx.x;
    const u32 dbase = sb + OFF_STAGE + par * STAGE_ROW_BYTES;
    {
        const int g = tid;                 // 0..511
        const int c = g / 34, j = g - c * 34;
        const int px0 = x0 - 4 + 4 * j;
        const bool ok = rowOK && (px0 >= 0) && (px0 <= 252);
        const float* src = xrow + ((u32)c << 16) + (ok ? px0 : 0);
        cp_async16(dbase + g * 16, src, ok ? 16u : 0u);
    }
    if (tid < 32) {
        const int g = tid + 512;           // 512..543
        const int c = g / 34, j = g - c * 34;
        const int px0 = x0 - 4 + 4 * j;
        const bool ok = rowOK && (px0 >= 0) && (px0 <= 252);
        const float* src = xrow + ((u32)c << 16) + (ok ? px0 : 0);
        cp_async16(dbase + g * 16, src, ok ? 16u : 0u);
    }
}

// ---- build hi/lo panels for two staged input rows ----
__device__ __forceinline__ void build_pair(char* smem, int gy0, int gy1) {
    const int tid = threadIdx.x;
    const int which = tid >> 8;          // 0 or 1
    const int r = tid & 255;
    if (r < 130) {
        const int gy = which ? gy1 : gy0;
        const int slot = (gy + 1) & 3;
        const float* sv = (const float*)(smem + OFF_STAGE + which * STAGE_ROW_BYTES);
        __align__(16) __nv_bfloat16 hi[16], lo[16];
        #pragma unroll
        for (int c = 0; c < 16; ++c) {
            const float v = sv[c * 136 + r + 3];
            const __nv_bfloat16 h = __float2bfloat16(v);
            hi[c] = h;
            lo[c] = __float2bfloat16(v - __bfloat162float(h));
        }
        char* hp = smem + OFF_AHI + slot * PANEL_BYTES;
        char* lp = smem + OFF_ALO + slot * PANEL_BYTES;
        const u32 o0 = ADDRSWZ(r, 0);
        const u32 o1 = ADDRSWZ(r, 16);
        *(uint4*)(hp + o0) = *(const uint4*)hi;
        *(uint4*)(hp + o1) = *(const uint4*)(hi + 8);
        *(uint4*)(lp + o0) = *(const uint4*)lo;
        *(uint4*)(lp + o1) = *(const uint4*)(lo + 8);
    }
}

__global__ __launch_bounds__(512, 1)
void conv_mma_kernel(const float* __restrict__ x,
                     const float* __restrict__ w,
                     const float* __restrict__ bias,
                     float* __restrict__ out) {
    extern __shared__ char smem[];
    const u32 sb = smem_u32(smem);
    const int tid = threadIdx.x;
    const int wid = tid >> 5;
    const int lid = tid & 31;
    const int b  = blockIdx.z;
    const int x0 = blockIdx.x * 128;
    const int y0 = blockIdx.y * 16;

    // Stage first input-row pair while we build B tiles
    stage_row(sb, x, b, x0, y0 - 1, 0);
    stage_row(sb, x, b, x0, y0,     1);
    CP_COMMIT();

    // ---- Build B tiles: [var][pos = ky*3+kx][f row: 16 ch x 2B], swizzled ----
    #pragma unroll
    for (int i = 0; i < 2; ++i) {
        const int t = tid + i * 512;
        if (t < 576) {
            const int var = t / 288;          // 0 = w_hi, 1 = w_lo
            const int rem = t - var * 288;
            const int pos = rem >> 5;         // 0..8 (= ky*3+kx)
            const int f   = rem & 31;
            __align__(16) __nv_bfloat16 q[16];
            #pragma unroll
            for (int c = 0; c < 16; ++c) {
                const float val = w[(c * 9 + pos) * 32 + f];
                const __nv_bfloat16 h = __float2bfloat16(val);
                q[c] = (var == 0) ? h : __float2bfloat16(val - __bfloat162float(h));
            }
            char* bp = smem + OFF_B + (var * 9 + pos) * B_TILE;
            *(uint4*)(bp + ADDRSWZ(f, 0))  = *(const uint4*)q;
            *(uint4*)(bp + ADDRSWZ(f, 16)) = *(const uint4*)(q + 8);
        }
    }

    // ---- Prologue: build panels for input rows y0-1 .. y0+2 ----
    CP_WAIT0();
    __syncthreads();
    build_pair(smem, y0 - 1, y0);
    stage_row(sb, x, b, x0, y0 + 1, 0);
    stage_row(sb, x, b, x0, y0 + 2, 1);
    CP_COMMIT();
    CP_WAIT0();
    __syncthreads();
    build_pair(smem, y0 + 1, y0 + 2);

    // per-thread fragment address components (loop-invariant)
    const int rowSel = wid >> 3;
    const int m0     = (wid & 7) * 16;
    const int pxA    = m0 + (lid & 15);
    const u32 halfA  = (u32)((lid >> 4) << 4);
    u32 aRel[3];
    #pragma unroll
    for (int kx = 0; kx < 3; ++kx) aRel[kx] = ADDRSWZ(pxA + kx, halfA);
    const int f0 = (lid & 7) + ((lid & 16) >> 1);
    const u32 bRel = ADDRSWZ(f0, (u32)((lid & 8) << 1));

    float* ostage = (float*)(smem + OFF_OUT);

    #pragma unroll 1
    for (int p = 0; p < 8; ++p) {
        __syncthreads();   // panels visible; prior readout finished
        if (p < 7) {       // stage next pair, hides under MMA
            stage_row(sb, x, b, x0, y0 + 2 * p + 3, 0);
            stage_row(sb, x, b, x0, y0 + 2 * p + 4, 1);
            CP_COMMIT();
        }

        const int y = y0 + 2 * p + rowSel;

        float d[4][4];
        #pragma unroll
        for (int nt = 0; nt < 4; ++nt)
            #pragma unroll
            for (int j = 0; j < 4; ++j) d[nt][j] = 0.0f;

        #pragma unroll
        for (int ky = 0; ky < 3; ++ky) {
            const u32 aHiBase = sb + OFF_AHI + (u32)(((y + ky) & 3) * PANEL_BYTES);
            const u32 aLoBase = aHiBase + OFF_ALO;
            #pragma unroll
            for (int kx = 0; kx < 3; ++kx) {
                u32 ah[4], al[4];
                ldsm_x4(ah, aHiBase + aRel[kx]);
                ldsm_x4(al, aLoBase + aRel[kx]);

                const u32 bHi = sb + OFF_B + (u32)((ky * 3 + kx) * B_TILE);
                const u32 bLo = bHi + 9 * B_TILE;
                u32 bw[8], bl[8];
                ldsm_x4(bw,     bHi + bRel);
                ldsm_x4(bw + 4, bHi + bRel + 512);
                ldsm_x4(bl,     bLo + bRel);
                ldsm_x4(bl + 4, bLo + bRel + 512);

                #pragma unroll
                for (int nt = 0; nt < 4; ++nt) {
                    mma16816(d[nt], ah, bw + nt * 2);   // x_hi * w_hi
                    mma16816(d[nt], al, bw + nt * 2);   // x_lo * w_hi
                    mma16816(d[nt], ah, bl + nt * 2);   // x_hi * w_lo
                }
            }
        }

        // ---- epilogue stage 1: fragments -> smem (bank-conflict-free) ----
        {
            float* st = ostage + rowSel * OUT_Y_FLOATS;
            const int r = lid >> 2;
            const int c = (lid & 3) * 2;
            #pragma unroll
            for (int nt = 0; nt < 4; ++nt) {
                #pragma unroll
                for (int j = 0; j < 4; ++j) {
                    const int f  = nt * 8 + c + (j & 1);
                    const int px = m0 + r + ((j & 2) ? 8 : 0);
                    st[f * OUT_ROW_FLOATS + px] = d[nt][j];
                }
            }
        }
        __syncthreads();

        // ---- epilogue stage 2: coalesced bias + sigmoid + store ----
        {
            #pragma unroll
            for (int i = 0; i < 4; ++i) {
                const int q  = wid + 16 * i;          // 0..63
                const int yr = q >> 5;                // 0/1
                const int f  = q & 31;
                const int yy = y0 + 2 * p + yr;
                const float* row = ostage + yr * OUT_Y_FLOATS + f * OUT_ROW_FLOATS;
                const int px0 = lid * 4;
                float4 v  = *(const float4*)(row + px0);
                const int pix = (yy << 8) + x0 + px0;
                float4 bv = *(const float4*)(bias + (f << 16) + pix);
                float4 o;
                o.x = __fdividef(1.0f, 1.0f + __expf(-(v.x + bv.x)));
                o.y = __fdividef(1.0f, 1.0f + __expf(-(v.y + bv.y)));
                o.z = __fdividef(1.0f, 1.0f + __expf(-(v.z + bv.z)));
                o.w = __fdividef(1.0f, 1.0f + __expf(-(v.w + bv.w)));
                *(float4*)(out + (((b << 5) + f) << 16) + pix) = o;
            }
        }

        if (p < 7) {
            CP_WAIT0();
            __syncthreads();   // panels free + staging landed + readout done
            build_pair(smem, y0 + 2 * p + 3, y0 + 2 * p + 4);
        }
    }
}

extern "C" void kernel_launch(void* const* d_in, const int* in_sizes, int n_in,
                              void* d_out, int out_size) {
    const float* x    = (const float*)d_in[0];   // (16,16,256,256)
    const float* w    = (const float*)d_in[1];   // (144,32)
    const float* bias = (const float*)d_in[2];   // (32,256,256)
    float* out = (float*)d_out;                  // (16,32,256,256)

    cudaFuncSetAttribute(conv_mma_kernel,
                         cudaFuncAttributeMaxDynamicSharedMemorySize, SMEM_TOTAL);

    dim3 grid(2, 16, 16);   // x-tiles, y-tiles, batch
    conv_mma_kernel<<<grid, 512, SMEM_TOTAL>>>(x, w, bias, out);
}

// round 15
// speedup vs baseline: 1.1195x; 1.1195x over previous
#include <cuda_runtime.h>
#include <cuda_bf16.h>
#include <cstdint>

typedef uint32_t u32;

// ---- smem layout (bytes) ----
#define PANEL_BYTES 4224                        // 132 rows x 32B (16ch bf16)
#define OFF_AHI 0                               // ring of 4 input rows (hi)
#define OFF_ALO (4 * PANEL_BYTES)               // 16896 (lo ring)
#define OFF_B   (8 * PANEL_BYTES)               // 33792: [2 var][9 pos][32 f][32B]
#define B_TILE  1024
#define OFF_STAGE (OFF_B + 18 * B_TILE)         // 52224
#define STAGE_ROW_BYTES 8704                    // 16 ch x 34 x 16B
#define SMEM_TOTAL (OFF_STAGE + 2 * STAGE_ROW_BYTES)   // 69632  (2 CTAs/SM)

// row/half -> swizzled byte offset inside a 32B-row panel (conflict-free LDSM)
#define ADDRSWZ(r, half16) ((((u32)(r) << 5) + (half16)) ^ (((r) & 4) << 2))

#define CP_COMMIT() asm volatile("cp.async.commit_group;" ::: "memory")
#define CP_WAIT0()  asm volatile("cp.async.wait_group 0;" ::: "memory")

__device__ __forceinline__ u32 smem_u32(const void* p) {
    u32 a;
    asm("{ .reg .u64 t; cvta.to.shared.u64 t, %1; cvt.u32.u64 %0, t; }" : "=r"(a) : "l"(p));
    return a;
}

__device__ __forceinline__ void cp_async16(u32 dst, const void* src, u32 bytes) {
    asm volatile("cp.async.ca.shared.global [%0], [%1], 16, %2;"
                 :: "r"(dst), "l"(src), "r"(bytes) : "memory");
}

__device__ __forceinline__ void ldsm_x4(u32* r, u32 addr) {
    asm volatile("ldmatrix.sync.aligned.m8n8.x4.shared.b16 {%0,%1,%2,%3}, [%4];"
                 : "=r"(r[0]), "=r"(r[1]), "=r"(r[2]), "=r"(r[3]) : "r"(addr));
}

__device__ __forceinline__ void mma16816(float* d, const u32* a, const u32* b) {
    asm volatile(
        "mma.sync.aligned.m16n8k16.row.col.f32.bf16.bf16.f32 "
        "{%0,%1,%2,%3}, {%4,%5,%6,%7}, {%8,%9}, {%0,%1,%2,%3};"
        : "+f"(d[0]), "+f"(d[1]), "+f"(d[2]), "+f"(d[3])
        : "r"(a[0]), "r"(a[1]), "r"(a[2]), "r"(a[3]), "r"(b[0]), "r"(b[1]));
}

// ---- stage one raw input row (16 ch x 136 px window) via cp.async, 256 thr ----
__device__ __forceinline__ void stage_row(u32 sb, const float* __restrict__ x,
                                          int b, int x0, int gy, int par) {
    const bool rowOK = (gy >= 0) && (gy < 256);
    const int gyc = rowOK ? gy : 0;
    const float* xrow = x + (((u32)b * 16) << 16) + (gyc << 8);
    const u32 dbase = sb + OFF_STAGE + par * STAGE_ROW_BYTES;
    #pragma unroll
    for (int i = 0; i < 3; ++i) {
        const int g = threadIdx.x + i * 256;   // 0..767, use < 544
        if (g < 544) {
            const int c = g / 34, j = g - c * 34;
            const int px0 = x0 - 4 + 4 * j;
            const bool ok = rowOK && (px0 >= 0) && (px0 <= 252);
            const float* src = xrow + ((u32)c << 16) + (ok ? px0 : 0);
            cp_async16(dbase + g * 16, src, ok ? 16u : 0u);
        }
    }
}

// ---- build hi/lo panel for one staged input row (threads 0..129) ----
__device__ __forceinline__ void build_row(char* smem, int gy, int par) {
    const int r = threadIdx.x;
    if (r < 130) {
        const int slot = (gy + 1) & 3;
        const float* sv = (const float*)(smem + OFF_STAGE + par * STAGE_ROW_BYTES);
        __align__(16) __nv_bfloat16 hi[16], lo[16];
        #pragma unroll
        for (int c = 0; c < 16; ++c) {
            const float v = sv[c * 136 + r + 3];
            const __nv_bfloat16 h = __float2bfloat16(v);
            hi[c] = h;
            lo[c] = __float2bfloat16(v - __bfloat162float(h));
        }
        char* hp = smem + OFF_AHI + slot * PANEL_BYTES;
        char* lp = smem + OFF_ALO + slot * PANEL_BYTES;
        const u32 o0 = ADDRSWZ(r, 0);
        const u32 o1 = ADDRSWZ(r, 16);
        *(uint4*)(hp + o0) = *(const uint4*)hi;
        *(uint4*)(hp + o1) = *(const uint4*)(hi + 8);
        *(uint4*)(lp + o0) = *(const uint4*)lo;
        *(uint4*)(lp + o1) = *(const uint4*)(lo + 8);
    }
}

__global__ __launch_bounds__(256, 2)
void conv_mma_kernel(const float* __restrict__ x,
                     const float* __restrict__ w,
                     const float* __restrict__ bias,
                     float* __restrict__ out) {
    extern __shared__ char smem[];
    const u32 sb = smem_u32(smem);
    const int tid = threadIdx.x;
    const int wid = tid >> 5;        // 0..7
    const int lid = tid & 31;
    const int b  = blockIdx.z;
    const int x0 = blockIdx.x * 128;
    const int y0 = blockIdx.y * 16;

    // Stage first input rows while we build B tiles
    stage_row(sb, x, b, x0, y0 - 1, 0);
    stage_row(sb, x, b, x0, y0,     1);
    CP_COMMIT();

    // ---- Build B tiles: [var][pos = ky*3+kx][f row: 16 ch x 2B], swizzled ----
    #pragma unroll
    for (int i = 0; i < 3; ++i) {
        const int t = tid + i * 256;         // 0..767, use < 576
        if (t < 576) {
            const int var = t / 288;          // 0 = w_hi, 1 = w_lo
            const int rem = t - var * 288;
            const int pos = rem >> 5;         // 0..8 (= ky*3+kx)
            const int f   = rem & 31;
            __align__(16) __nv_bfloat16 q[16];
            #pragma unroll
            for (int c = 0; c < 16; ++c) {
                const float val = w[(c * 9 + pos) * 32 + f];
                const __nv_bfloat16 h = __float2bfloat16(val);
                q[c] = (var == 0) ? h : __float2bfloat16(val - __bfloat162float(h));
            }
            char* bp = smem + OFF_B + (var * 9 + pos) * B_TILE;
            *(uint4*)(bp + ADDRSWZ(f, 0))  = *(const uint4*)q;
            *(uint4*)(bp + ADDRSWZ(f, 16)) = *(const uint4*)(q + 8);
        }
    }

    // ---- Prologue: panels for input rows y0-1, y0, y0+1 ----
    CP_WAIT0();
    __syncthreads();
    build_row(smem, y0 - 1, 0);
    build_row(smem, y0,     1);
    __syncthreads();   // RACE FIX: slot-0 readers must finish before re-staging slot 0
    stage_row(sb, x, b, x0, y0 + 1, 0);
    CP_COMMIT();
    CP_WAIT0();
    __syncthreads();
    build_row(smem, y0 + 1, 0);

    // per-warp fragment address components (loop-invariant)
    const int m0  = wid * 16;
    const int pxA = m0 + (lid & 15);
    const u32 halfA = (u32)((lid >> 4) << 4);
    u32 aRel[3];
    #pragma unroll
    for (int kx = 0; kx < 3; ++kx) aRel[kx] = ADDRSWZ(pxA + kx, halfA);
    const int f0 = (lid & 7) + ((lid & 16) >> 1);
    const u32 bRel = ADDRSWZ(f0, (u32)((lid & 8) << 1));

    #pragma unroll 1
    for (int p = 0; p < 16; ++p) {
        __syncthreads();   // panel for row y0+p+1 visible; prior slot readers done
        if (p < 15) {      // stage next raw row; hides under MMA
            stage_row(sb, x, b, x0, y0 + p + 2, p & 1);
            CP_COMMIT();
        }

        const int y = y0 + p;

        float d[4][4];
        #pragma unroll
        for (int nt = 0; nt < 4; ++nt)
            #pragma unroll
            for (int j = 0; j < 4; ++j) d[nt][j] = 0.0f;

        #pragma unroll
        for (int ky = 0; ky < 3; ++ky) {
            const u32 aHiBase = sb + OFF_AHI + (u32)(((y + ky) & 3) * PANEL_BYTES);
            const u32 aLoBase = aHiBase + OFF_ALO;
            #pragma unroll
            for (int kx = 0; kx < 3; ++kx) {
                u32 ah[4], al[4];
                ldsm_x4(ah, aHiBase + aRel[kx]);
                ldsm_x4(al, aLoBase + aRel[kx]);

                const u32 bHi = sb + OFF_B + (u32)((ky * 3 + kx) * B_TILE);
                const u32 bLo = bHi + 9 * B_TILE;
                u32 bw[8], bl[8];
                ldsm_x4(bw,     bHi + bRel);
                ldsm_x4(bw + 4, bHi + bRel + 512);
                ldsm_x4(bl,     bLo + bRel);
                ldsm_x4(bl + 4, bLo + bRel + 512);

                #pragma unroll
                for (int nt = 0; nt < 4; ++nt) {
                    mma16816(d[nt], ah, bw + nt * 2);   // x_hi * w_hi
                    mma16816(d[nt], al, bw + nt * 2);   // x_lo * w_hi
                    mma16816(d[nt], ah, bl + nt * 2);   // x_hi * w_lo
                }
            }
        }

        // ---- epilogue: bias + sigmoid + store (direct) ----
        {
            const int r = lid >> 2;
            const int c = (lid & 3) * 2;
            const int pixA = (y << 8) + x0 + m0 + r;
            const int pixB = pixA + 8;
            #pragma unroll
            for (int nt = 0; nt < 4; ++nt) {
                #pragma unroll
                for (int j = 0; j < 4; ++j) {
                    const int f   = nt * 8 + c + (j & 1);
                    const int pix = (j & 2) ? pixB : pixA;
                    const float v = d[nt][j] + bias[(f << 16) + pix];
                    out[(((b << 5) + f) << 16) + pix] =
                        __fdividef(1.0f, 1.0f + __expf(-v));
                }
            }
        }

        if (p < 15) {
            CP_WAIT0();
            __syncthreads();   // readers done with old panels + staging landed
            build_row(smem, y0 + p + 2, p & 1);
        }
    }
}

extern "C" void kernel_launch(void* const* d_in, const int* in_sizes, int n_in,
                              void* d_out, int out_size) {
    const float* x    = (const float*)d_in[0];   // (16,16,256,256)
    const float* w    = (const float*)d_in[1];   // (144,32)
    const float* bias = (const float*)d_in[2];   // (32,256,256)
    float* out = (float*)d_out;                  // (16,32,256,256)

    cudaFuncSetAttribute(conv_mma_kernel,
                         cudaFuncAttributeMaxDynamicSharedMemorySize, SMEM_TOTAL);

    dim3 grid(2, 16, 16);   // x-tiles, y-tiles, batch
    conv_mma_kernel<<<grid, 256, SMEM_TOTAL>>>(x, w, bias, out);
}